// round 9
// baseline (speedup 1.0000x reference)
#include <cuda_runtime.h>
#include <cuda_bf16.h>
#include <cstdint>

#define CND   256
#define VN    4096
#define NPTS  32768
#define PB    4096
#define A_ELEMS (NPTS * CND)

#define MT      128                // points per CTA
#define TV      128                // codewords per V-tile
#define KCHUNK  32
#define NSTAGES 256                // (VN/TV) * (CND/KCHUNK) = 32*8
#define THREADS 512
#define NB_VQ   256
#define NB_FN   256
#define NCAND   6

// smem layout (halves / floats)
#define SXS 264                    // sx row stride in bf16 (132 words: banks 4*ra+ka)
#define SWS 40                     // sw row stride in bf16 (20 words: banks 20*ra+ka)
#define MRS 132                    // merge row stride in words ([slot][MRS])
#define OFF_SX  0                  // 128*264*2  = 67584
#define OFF_SW  67584              // 2*128*40*2 = 20480
#define OFF_SCR 88064              // 32*132*4   = 16896
#define OFF_SID 104960             // 16896
#define SMEM_BYTES 121856

__device__ float  g_wsq[VN];
__device__ int    g_cand[NPTS * NCAND];
__device__ double g_blocksum[NB_FN];

__device__ __forceinline__ void mma_bf16(float c[4], const uint32_t a[4],
                                         const uint32_t b2[2]) {
    asm volatile(
        "mma.sync.aligned.m16n8k16.row.col.f32.bf16.bf16.f32 "
        "{%0,%1,%2,%3}, {%4,%5,%6,%7}, {%8,%9}, {%0,%1,%2,%3};"
        : "+f"(c[0]), "+f"(c[1]), "+f"(c[2]), "+f"(c[3])
        : "r"(a[0]), "r"(a[1]), "r"(a[2]), "r"(a[3]), "r"(b2[0]), "r"(b2[1]));
}

// ---------------------------------------------------------------------------
// Kernel 0: ||w_v||^2, one warp per row
// ---------------------------------------------------------------------------
__global__ __launch_bounds__(256)
void wsq_kernel(const float* __restrict__ W) {
    const int warp = (blockIdx.x * 8) + (threadIdx.x >> 5);
    const int lane = threadIdx.x & 31;
    const float4* row = reinterpret_cast<const float4*>(W + (size_t)warp * CND);
    float4 u = row[lane];
    float4 v = row[lane + 32];
    float s = u.x*u.x + u.y*u.y + u.z*u.z + u.w*u.w
            + v.x*v.x + v.y*v.y + v.z*v.z + v.w*v.w;
    #pragma unroll
    for (int o = 16; o > 0; o >>= 1) s += __shfl_down_sync(0xFFFFFFFF, s, o);
    if (lane == 0) g_wsq[warp] = s;
}

// ---------------------------------------------------------------------------
// Split W staging: LDG (registers) early, STS late -> overlaps gmem latency
// with the MMA loop. Each of 512 threads owns 8 floats of the 128x32 chunk.
// ---------------------------------------------------------------------------
__device__ __forceinline__ void stage_w_load(const float* __restrict__ W,
                                             int s, int tid,
                                             float4& t0, float4& t1) {
    const int vt = s >> 3, kc = s & 7;
    const int v = tid >> 2, q = tid & 3;
    const float4* src = reinterpret_cast<const float4*>(
        W + (size_t)(vt * TV + v) * CND + kc * KCHUNK + q * 8);
    t0 = src[0];
    t1 = src[1];
}

__device__ __forceinline__ void stage_w_store(__nv_bfloat16* sw, int s, int tid,
                                              const float4& t0, const float4& t1) {
    const int v = tid >> 2, q = tid & 3;
    __nv_bfloat16* dst = sw + (s & 1) * (TV * SWS) + v * SWS + q * 8;
    __nv_bfloat162 h0 = __floats2bfloat162_rn(t0.x, t0.y);
    __nv_bfloat162 h1 = __floats2bfloat162_rn(t0.z, t0.w);
    __nv_bfloat162 h2 = __floats2bfloat162_rn(t1.x, t1.y);
    __nv_bfloat162 h3 = __floats2bfloat162_rn(t1.z, t1.w);
    uint4 u;
    u.x = *reinterpret_cast<uint32_t*>(&h0);
    u.y = *reinterpret_cast<uint32_t*>(&h1);
    u.z = *reinterpret_cast<uint32_t*>(&h2);
    u.w = *reinterpret_cast<uint32_t*>(&h3);
    *reinterpret_cast<uint4*>(dst) = u;
}

// ---------------------------------------------------------------------------
// Kernel 1: bf16 mma.sync distance GEMM, 16 warps (4 wM x 4 wN), 32x32/warp.
// Per V-tile: per-thread slot top-2 -> single publish -> global top-6.
// ---------------------------------------------------------------------------
__global__ __launch_bounds__(THREADS, 1)
void vq_mma_kernel(const float* __restrict__ G, const float* __restrict__ W) {
    extern __shared__ char smem[];
    __nv_bfloat16* sx  = reinterpret_cast<__nv_bfloat16*>(smem + OFF_SX);
    __nv_bfloat16* sw  = reinterpret_cast<__nv_bfloat16*>(smem + OFF_SW);
    float*         scr = reinterpret_cast<float*>(smem + OFF_SCR);
    int*           sid = reinterpret_cast<int*>(smem + OFF_SID);

    const int tid  = threadIdx.x;
    const int wid  = tid >> 5;
    const int lane = tid & 31;
    const int ka   = lane & 3;
    const int ra   = lane >> 2;
    const int wM   = wid & 3;      // 4 M-groups of 32 rows
    const int wN   = wid >> 2;     // 4 N-groups of 32 cols
    const int n0   = blockIdx.x * MT;
    const int b    = n0 / PB;
    const int p0   = n0 % PB;

    // Stage A: G [c][p] -> sx [m][k] bf16
    {
        const float* Gb = G + (size_t)b * CND * PB + p0;
        const int p = tid & 127, ch = tid >> 7;   // ch in 0..3 -> 64 channels
        __nv_bfloat16* dst = sx + p * SXS;
        #pragma unroll 4
        for (int c4 = 0; c4 < 16; c4++) {
            const int c = ch * 64 + c4 * 4;
            float x0 = Gb[(size_t)(c + 0) * PB + p];
            float x1 = Gb[(size_t)(c + 1) * PB + p];
            float x2 = Gb[(size_t)(c + 2) * PB + p];
            float x3 = Gb[(size_t)(c + 3) * PB + p];
            __nv_bfloat162 h01 = __floats2bfloat162_rn(x0, x1);
            __nv_bfloat162 h23 = __floats2bfloat162_rn(x2, x3);
            uint2 u;
            u.x = *reinterpret_cast<uint32_t*>(&h01);
            u.y = *reinterpret_cast<uint32_t*>(&h23);
            *reinterpret_cast<uint2*>(dst + c) = u;
        }
    }
    {
        float4 w0, w1;
        stage_w_load(W, 0, tid, w0, w1);
        stage_w_store(sw, 0, tid, w0, w1);
    }
    __syncthreads();

    float acc[2][4][4];
    #pragma unroll
    for (int mt = 0; mt < 2; mt++)
        #pragma unroll
        for (int nt = 0; nt < 4; nt++)
            #pragma unroll
            for (int i = 0; i < 4; i++) acc[mt][nt][i] = 0.f;

    float bs[NCAND]; int bi[NCAND];
    #pragma unroll
    for (int q = 0; q < NCAND; q++) { bs[q] = 3.4e38f; bi[q] = 0; }

    #pragma unroll 1
    for (int s = 0; s < NSTAGES; s++) {
        // issue next-stage W loads early; latency overlapped by MMA loop
        float4 w0, w1;
        const bool has_next = (s + 1 < NSTAGES);
        if (has_next) stage_w_load(W, s + 1, tid, w0, w1);

        const __nv_bfloat16* swb = sw + (s & 1) * (TV * SWS);
        const int kc = s & 7;
        #pragma unroll
        for (int kk = 0; kk < 2; kk++) {
            const int kb = kc * KCHUNK + kk * 16;
            uint32_t af[2][4];
            #pragma unroll
            for (int mt = 0; mt < 2; mt++) {
                const int m = wM * 32 + mt * 16 + ra;
                const __nv_bfloat16* r0 = sx + m * SXS + kb + 2 * ka;
                const __nv_bfloat16* r1 = r0 + 8 * SXS;
                af[mt][0] = *reinterpret_cast<const uint32_t*>(r0);
                af[mt][1] = *reinterpret_cast<const uint32_t*>(r1);
                af[mt][2] = *reinterpret_cast<const uint32_t*>(r0 + 8);
                af[mt][3] = *reinterpret_cast<const uint32_t*>(r1 + 8);
            }
            uint32_t bf[4][2];
            #pragma unroll
            for (int nt = 0; nt < 4; nt++) {
                const __nv_bfloat16* br =
                    swb + (wN * 32 + nt * 8 + ra) * SWS + kk * 16 + 2 * ka;
                bf[nt][0] = *reinterpret_cast<const uint32_t*>(br);
                bf[nt][1] = *reinterpret_cast<const uint32_t*>(br + 8);
            }
            #pragma unroll
            for (int mt = 0; mt < 2; mt++)
                #pragma unroll
                for (int nt = 0; nt < 4; nt++)
                    mma_bf16(acc[mt][nt], af[mt], bf[nt]);
        }

        if (kc == 7) {
            const int vt = s >> 3;
            const int slot = wN * 4 + ka;
            // per-row top-2 over this thread's 8 cols; publish both halves
            #pragma unroll
            for (int mt = 0; mt < 2; mt++) {
                #pragma unroll
                for (int h = 0; h < 2; h++) {
                    const int r = wM * 32 + mt * 16 + ra + 8 * h;
                    float b1 = 3.4e38f, b2 = 3.4e38f; int j1 = 0, j2 = 0;
                    #pragma unroll
                    for (int nt = 0; nt < 4; nt++) {
                        const int cb = vt * TV + wN * 32 + nt * 8 + 2 * ka;
                        const float ea = fmaf(-2.f, acc[mt][nt][2*h],   __ldg(&g_wsq[cb]));
                        const float eb = fmaf(-2.f, acc[mt][nt][2*h+1], __ldg(&g_wsq[cb+1]));
                        if (ea < b2) {
                            if (ea < b1) { b2 = b1; j2 = j1; b1 = ea; j1 = cb; }
                            else         { b2 = ea; j2 = cb; }
                        }
                        if (eb < b2) {
                            if (eb < b1) { b2 = b1; j2 = j1; b1 = eb; j1 = cb + 1; }
                            else         { b2 = eb; j2 = cb + 1; }
                        }
                    }
                    scr[slot * MRS + r]        = b1;  sid[slot * MRS + r]        = j1;
                    scr[(slot + 16) * MRS + r] = b2;  sid[(slot + 16) * MRS + r] = j2;
                }
            }
            #pragma unroll
            for (int mt = 0; mt < 2; mt++)
                #pragma unroll
                for (int nt = 0; nt < 4; nt++)
                    acc[mt][nt][0] = acc[mt][nt][1] = acc[mt][nt][2] = acc[mt][nt][3] = 0.f;
            __syncthreads();
            if (tid < MT) {
                #pragma unroll 1
                for (int t = 0; t < 32; t++) {
                    float cs = scr[t * MRS + tid]; int ci = sid[t * MRS + tid];
                    if (cs < bs[NCAND - 1]) {
                        #pragma unroll
                        for (int q = 0; q < NCAND; q++)
                            if (cs < bs[q]) {
                                float ts = bs[q]; int ti = bi[q];
                                bs[q] = cs; bi[q] = ci; cs = ts; ci = ti;
                            }
                    }
                }
            }
        }

        // store next-stage W into the other buffer (current MMAs all done for
        // this warp; other warps read buffer s&1, we write (s+1)&1)
        if (has_next) stage_w_store(sw, s + 1, tid, w0, w1);
        __syncthreads();
    }

    if (tid < MT) {
        const int n = n0 + tid;
        #pragma unroll
        for (int q = 0; q < NCAND; q++) g_cand[n * NCAND + q] = bi[q];
    }
}

// ---------------------------------------------------------------------------
// Kernel 2 (fused): exact fp32 rescore of 6 candidates -> argmin, scatter,
// MSE via gsq - 2*dot + wsq (fp64 combine)
// ---------------------------------------------------------------------------
__global__ __launch_bounds__(128)
void finalize_kernel(const float* __restrict__ G, const float* __restrict__ W,
                     float* __restrict__ out) {
    const int n = blockIdx.x * 128 + threadIdx.x;
    const int b = n / PB, p = n % PB;
    const float* g = G + (size_t)b * CND * PB + p;

    int v[NCAND];
    #pragma unroll
    for (int j = 0; j < NCAND; j++) v[j] = g_cand[n * NCAND + j];

    const float* wr0 = W + (size_t)v[0] * CND;
    const float* wr1 = W + (size_t)v[1] * CND;
    const float* wr2 = W + (size_t)v[2] * CND;
    const float* wr3 = W + (size_t)v[3] * CND;
    const float* wr4 = W + (size_t)v[4] * CND;
    const float* wr5 = W + (size_t)v[5] * CND;

    float dot[NCAND] = {0.f, 0.f, 0.f, 0.f, 0.f, 0.f};
    float gsq = 0.f;
    #pragma unroll 4
    for (int c = 0; c < CND; c++) {
        const float x = g[(size_t)c * PB];
        gsq    = fmaf(x, x, gsq);
        dot[0] = fmaf(x, __ldg(wr0 + c), dot[0]);
        dot[1] = fmaf(x, __ldg(wr1 + c), dot[1]);
        dot[2] = fmaf(x, __ldg(wr2 + c), dot[2]);
        dot[3] = fmaf(x, __ldg(wr3 + c), dot[3]);
        dot[4] = fmaf(x, __ldg(wr4 + c), dot[4]);
        dot[5] = fmaf(x, __ldg(wr5 + c), dot[5]);
    }

    float bsx = 3.4e38f; int bix = 0x7fffffff; float bdot = 0.f, bwsq = 0.f;
    #pragma unroll
    for (int j = 0; j < NCAND; j++) {
        const float ws = g_wsq[v[j]];
        const float sc = ws - 2.f * dot[j];
        if (sc < bsx || (sc == bsx && v[j] < bix)) {
            bsx = sc; bix = v[j]; bdot = dot[j]; bwsq = ws;
        }
    }

    out[2 * (size_t)A_ELEMS + n] = (float)bix;

    const float* wbest = W + (size_t)bix * CND;
    float* q1 = out + (size_t)b * CND * PB + p;
    float* q2 = q1 + (size_t)A_ELEMS;
    #pragma unroll 4
    for (int c = 0; c < CND; c++) {
        const float w = __ldg(wbest + c);
        q1[(size_t)c * PB] = w;
        q2[(size_t)c * PB] = w;
    }

    const double d2 = (double)gsq - 2.0 * (double)bdot + (double)bwsq;

    __shared__ double sred[128];
    sred[threadIdx.x] = d2;
    __syncthreads();
    for (int st = 64; st > 0; st >>= 1) {
        if (threadIdx.x < st) sred[threadIdx.x] += sred[threadIdx.x + st];
        __syncthreads();
    }
    if (threadIdx.x == 0) g_blocksum[blockIdx.x] = sred[0];
}

__global__ void final_kernel(float* __restrict__ out) {
    double s = 0.0;
    for (int i = 0; i < NB_FN; i++) s += g_blocksum[i];
    out[2 * (size_t)A_ELEMS + NPTS] = (float)(s / ((double)NPTS * (double)CND));
}

// ---------------------------------------------------------------------------
// Launch
// ---------------------------------------------------------------------------
extern "C" void kernel_launch(void* const* d_in, const int* in_sizes, int n_in,
                              void* d_out, int out_size) {
    const float* G = (const float*)d_in[0];
    const float* W = (const float*)d_in[1];
    float* out = (float*)d_out;

    cudaFuncSetAttribute(vq_mma_kernel,
                         cudaFuncAttributeMaxDynamicSharedMemorySize, SMEM_BYTES);

    wsq_kernel<<<VN / 8, 256>>>(W);
    vq_mma_kernel<<<NB_VQ, THREADS, SMEM_BYTES>>>(G, W);
    finalize_kernel<<<NB_FN, 128>>>(G, W, out);
    final_kernel<<<1, 1>>>(out);
}